// round 2
// baseline (speedup 1.0000x reference)
#include <cuda_runtime.h>
#include <math.h>

#define NMAX 20000
#define DIM 512
#define H1 8
#define C1 64

// ---------------- scratch (static device memory; no allocations) -------------
__device__ float g_bufA[NMAX * DIM];   // GEMM outputs / GAT feature h
__device__ float g_bufB[NMAX * DIM];   // GAT aggregation output
__device__ float g_bufC[NMAX * DIM];   // fc output (post-relu)
__device__ float g_bufD[NMAX * DIM];   // BN output
__device__ float g_als[NMAX * H1];
__device__ float g_ald[NMAX * H1];
__device__ float g_m[NMAX * H1];
__device__ float g_s[NMAX * H1];
__device__ float g_sum[DIM];
__device__ float g_sumsq[DIM];

// ---------------- helpers ----------------------------------------------------
__device__ __forceinline__ void atomicMaxFloat(float* addr, float val) {
    int old = __float_as_int(*addr);
    while (__int_as_float(old) < val) {
        int assumed = old;
        old = atomicCAS((int*)addr, assumed, __float_as_int(val));
        if (old == assumed) break;
    }
}

// ---------------- GEMM: C[M,N] = A[M,K] @ B[K,N] (+bias)(+relu) --------------
// 64x64 tile, BK=16, 256 threads, 4x4 per thread. K%16==0, N%64==0 assumed.
__global__ __launch_bounds__(256) void gemm64(
    const float* __restrict__ A, const float* __restrict__ B,
    const float* __restrict__ bias, float* __restrict__ C,
    int M, int N, int K, int has_bias, int do_relu)
{
    __shared__ float As[16][65];
    __shared__ float Bs[16][64];

    int tid = threadIdx.x;
    int tx = tid & 15;       // 0..15 -> 4 cols each
    int ty = tid >> 4;       // 0..15 -> 4 rows each
    int m0 = blockIdx.y * 64;
    int n0 = blockIdx.x * 64;

    float acc[4][4];
#pragma unroll
    for (int i = 0; i < 4; i++)
#pragma unroll
        for (int j = 0; j < 4; j++) acc[i][j] = 0.f;

    for (int k0 = 0; k0 < K; k0 += 16) {
        // load A tile (64 rows x 16 cols), store transposed
#pragma unroll
        for (int l = 0; l < 4; l++) {
            int idx = tid + l * 256;
            int ar = idx >> 4;      // 0..63
            int ac = idx & 15;      // 0..15
            int gm = m0 + ar;
            float v = (gm < M) ? A[(size_t)gm * K + k0 + ac] : 0.f;
            As[ac][ar] = v;
        }
        // load B tile (16 rows x 64 cols)
#pragma unroll
        for (int l = 0; l < 4; l++) {
            int idx = tid + l * 256;
            int br = idx >> 6;      // 0..15
            int bc = idx & 63;      // 0..63
            Bs[br][bc] = B[(size_t)(k0 + br) * N + n0 + bc];
        }
        __syncthreads();

#pragma unroll
        for (int kk = 0; kk < 16; kk++) {
            float a[4], b[4];
#pragma unroll
            for (int i = 0; i < 4; i++) a[i] = As[kk][ty * 4 + i];
#pragma unroll
            for (int j = 0; j < 4; j++) b[j] = Bs[kk][tx * 4 + j];
#pragma unroll
            for (int i = 0; i < 4; i++)
#pragma unroll
                for (int j = 0; j < 4; j++) acc[i][j] = fmaf(a[i], b[j], acc[i][j]);
        }
        __syncthreads();
    }

#pragma unroll
    for (int i = 0; i < 4; i++) {
        int gm = m0 + ty * 4 + i;
        if (gm >= M) continue;
#pragma unroll
        for (int j = 0; j < 4; j++) {
            int gn = n0 + tx * 4 + j;
            float v = acc[i][j];
            if (has_bias) v += bias[gn];
            if (do_relu) v = fmaxf(v, 0.f);
            C[(size_t)gm * N + gn] = v;
        }
    }
}

// -------- attention logits, H=8 heads of C=64: one block per node ------------
__global__ void attn_logits8(const float* __restrict__ h,
                             const float* __restrict__ a_s,
                             const float* __restrict__ a_d,
                             float* __restrict__ als, float* __restrict__ ald, int n)
{
    int node = blockIdx.x;
    if (node >= n) return;
    int w = threadIdx.x >> 5;
    int lane = threadIdx.x & 31;
    const float* row = h + (size_t)node * DIM + w * C1;
    float ss = 0.f, sd = 0.f;
#pragma unroll
    for (int c = lane; c < C1; c += 32) {
        float v = row[c];
        ss = fmaf(v, a_s[w * C1 + c], ss);
        sd = fmaf(v, a_d[w * C1 + c], sd);
    }
#pragma unroll
    for (int o = 16; o; o >>= 1) {
        ss += __shfl_down_sync(0xffffffffu, ss, o);
        sd += __shfl_down_sync(0xffffffffu, sd, o);
    }
    if (lane == 0) { als[node * 8 + w] = ss; ald[node * 8 + w] = sd; }
}

// -------- attention logits, H=1, C=512: one warp per node --------------------
__global__ void attn_logits1(const float* __restrict__ h,
                             const float* __restrict__ a_s,
                             const float* __restrict__ a_d,
                             float* __restrict__ als, float* __restrict__ ald, int n)
{
    int warp = (blockIdx.x * blockDim.x + threadIdx.x) >> 5;
    int lane = threadIdx.x & 31;
    if (warp >= n) return;
    const float* row = h + (size_t)warp * DIM;
    float ss = 0.f, sd = 0.f;
#pragma unroll 4
    for (int c = lane; c < DIM; c += 32) {
        float v = row[c];
        ss = fmaf(v, a_s[c], ss);
        sd = fmaf(v, a_d[c], sd);
    }
#pragma unroll
    for (int o = 16; o; o >>= 1) {
        ss += __shfl_down_sync(0xffffffffu, ss, o);
        sd += __shfl_down_sync(0xffffffffu, sd, o);
    }
    if (lane == 0) { als[warp] = ss; ald[warp] = sd; }
}

// -------- init: m = -inf, s = 0, out row = bias -------------------------------
__global__ void init_layer(float* __restrict__ m, float* __restrict__ s, int nH,
                           float* __restrict__ out, const float* __restrict__ bias, int nD)
{
    int i = blockIdx.x * blockDim.x + threadIdx.x;
    if (i < nH) { m[i] = -1e30f; s[i] = 0.f; }
    if (i < nD) out[i] = bias[i & (DIM - 1)];
}

// -------- edge pass: 0 = segment max, 1 = segment sum of exp ------------------
// edge_index is int32 (JAX x64 disabled downcasts jnp.int64 -> int32).
__global__ void edge_pass(const int* __restrict__ ei, int E, int n,
                          const float* __restrict__ als, const float* __restrict__ ald,
                          float* __restrict__ m, float* __restrict__ s, int H, int pass)
{
    int idx = blockIdx.x * blockDim.x + threadIdx.x;
    int total = (E + n) * H;
    if (idx >= total) return;
    int e, hh;
    if (H == 8) { e = idx >> 3; hh = idx & 7; }
    else        { e = idx;      hh = 0; }
    int src, dst;
    if (e < E) { src = ei[e]; dst = ei[E + e]; }
    else       { src = dst = e - E; }
    float ev = als[src * H + hh] + ald[dst * H + hh];
    ev = (ev > 0.f) ? ev : 0.2f * ev;
    if (pass == 0) {
        atomicMaxFloat(&m[dst * H + hh], ev);
    } else {
        atomicAdd(&s[dst * H + hh], __expf(ev - m[dst * H + hh]));
    }
}

// -------- weighted scatter aggregation: 128 threads per edge ------------------
__global__ __launch_bounds__(256) void edge_agg(
    const int* __restrict__ ei, int E, int n,
    const float* __restrict__ h,
    const float* __restrict__ als, const float* __restrict__ ald,
    const float* __restrict__ m, const float* __restrict__ s,
    float* __restrict__ out, int H)
{
    int e = blockIdx.x * 2 + (threadIdx.x >> 7);
    int t = threadIdx.x & 127;
    if (e >= E + n) return;
    int src, dst;
    if (e < E) { src = ei[e]; dst = ei[E + e]; }
    else       { src = dst = e - E; }
    int d0 = t * 4;
    int hh = (H == 8) ? (d0 >> 6) : 0;
    float ev = als[src * H + hh] + ald[dst * H + hh];
    ev = (ev > 0.f) ? ev : 0.2f * ev;
    float w = __expf(ev - m[dst * H + hh]) / s[dst * H + hh];
    float4 v = *(const float4*)(h + (size_t)src * DIM + d0);
    float* o = out + (size_t)dst * DIM + d0;
    atomicAdd(o + 0, w * v.x);
    atomicAdd(o + 1, w * v.y);
    atomicAdd(o + 2, w * v.z);
    atomicAdd(o + 3, w * v.w);
}

// -------- BN: column stats then apply -----------------------------------------
__global__ void zero_stats() {
    int i = threadIdx.x;
    if (i < DIM) { g_sum[i] = 0.f; g_sumsq[i] = 0.f; }
}

__global__ void bn_stats(const float* __restrict__ x, int n)
{
    int col = blockIdx.x * 256 + threadIdx.x;   // gridDim.x == 2
    float sm = 0.f, sq = 0.f;
    for (int r = blockIdx.y; r < n; r += gridDim.y) {
        float v = x[(size_t)r * DIM + col];
        sm += v;
        sq = fmaf(v, v, sq);
    }
    atomicAdd(&g_sum[col], sm);
    atomicAdd(&g_sumsq[col], sq);
}

__global__ void bn_apply(const float* __restrict__ x,
                         const float* __restrict__ gamma, const float* __restrict__ beta,
                         float* __restrict__ y, int n)
{
    int i = blockIdx.x * blockDim.x + threadIdx.x;
    if (i >= n * DIM) return;
    int col = i & (DIM - 1);
    float inv_n = 1.f / (float)n;
    float mu = g_sum[col] * inv_n;
    float var = g_sumsq[col] * inv_n - mu * mu;
    y[i] = fmaf(gamma[col] * (x[i] - mu), rsqrtf(var + 1e-5f), beta[col]);
}

// -------- final linear [512 -> 2] + relu: one warp per node --------------------
__global__ void final_lin(const float* __restrict__ h, const float* __restrict__ w,
                          const float* __restrict__ b, float* __restrict__ out, int n)
{
    int warp = (blockIdx.x * blockDim.x + threadIdx.x) >> 5;
    int lane = threadIdx.x & 31;
    if (warp >= n) return;
    const float* row = h + (size_t)warp * DIM;
    float a0 = 0.f, a1 = 0.f;
#pragma unroll 4
    for (int c = lane; c < DIM; c += 32) {
        float v = row[c];
        a0 = fmaf(v, w[c * 2 + 0], a0);
        a1 = fmaf(v, w[c * 2 + 1], a1);
    }
#pragma unroll
    for (int o = 16; o; o >>= 1) {
        a0 += __shfl_down_sync(0xffffffffu, a0, o);
        a1 += __shfl_down_sync(0xffffffffu, a1, o);
    }
    if (lane == 0) {
        out[warp * 2 + 0] = fmaxf(a0 + b[0], 0.f);
        out[warp * 2 + 1] = fmaxf(a1 + b[1], 0.f);
    }
}

// ------------------------------------------------------------------------------
extern "C" void kernel_launch(void* const* d_in, const int* in_sizes, int n_in,
                              void* d_out, int out_size)
{
    const float* x    = (const float*)d_in[0];
    const int*   ei   = (const int*)d_in[1];     // int32 edge indices!
    const float* W1   = (const float*)d_in[2];
    const float* a1s  = (const float*)d_in[3];
    const float* a1d  = (const float*)d_in[4];
    const float* b1   = (const float*)d_in[5];
    const float* W2   = (const float*)d_in[6];
    const float* a2s  = (const float*)d_in[7];
    const float* a2d  = (const float*)d_in[8];
    const float* b2   = (const float*)d_in[9];
    const float* fc1w = (const float*)d_in[10];
    const float* fc1b = (const float*)d_in[11];
    const float* g1   = (const float*)d_in[12];
    const float* be1  = (const float*)d_in[13];
    const float* fc2w = (const float*)d_in[14];
    const float* fc2b = (const float*)d_in[15];
    const float* g2   = (const float*)d_in[16];
    const float* be2  = (const float*)d_in[17];
    const float* linw = (const float*)d_in[18];
    const float* linb = (const float*)d_in[19];
    float* out = (float*)d_out;

    int n = out_size / 2;        // 20000
    int E = in_sizes[1] / 2;     // 320000
    int Et = E + n;

    float *A, *B, *C, *Dd, *als, *ald, *mm, *ss;
    cudaGetSymbolAddress((void**)&A,   g_bufA);
    cudaGetSymbolAddress((void**)&B,   g_bufB);
    cudaGetSymbolAddress((void**)&C,   g_bufC);
    cudaGetSymbolAddress((void**)&Dd,  g_bufD);
    cudaGetSymbolAddress((void**)&als, g_als);
    cudaGetSymbolAddress((void**)&ald, g_ald);
    cudaGetSymbolAddress((void**)&mm,  g_m);
    cudaGetSymbolAddress((void**)&ss,  g_s);

    dim3 gemm_grid(DIM / 64, (n + 63) / 64);
    int nd_blocks = (n * DIM + 255) / 256;

    // ---------------- layer 1: GATConv(128 -> 8x64) ----------------
    gemm64<<<gemm_grid, 256>>>(x, W1, nullptr, A, n, DIM, 128, 0, 0);
    attn_logits8<<<n, 256>>>(A, a1s, a1d, als, ald, n);
    init_layer<<<nd_blocks, 256>>>(mm, ss, n * 8, B, b1, n * DIM);
    edge_pass<<<(Et * 8 + 255) / 256, 256>>>(ei, E, n, als, ald, mm, ss, 8, 0);
    edge_pass<<<(Et * 8 + 255) / 256, 256>>>(ei, E, n, als, ald, mm, ss, 8, 1);
    edge_agg<<<(Et + 1) / 2, 256>>>(ei, E, n, A, als, ald, mm, ss, B, 8);

    // ---------------- fc1 + relu + BN ----------------
    gemm64<<<gemm_grid, 256>>>(B, fc1w, fc1b, C, n, DIM, DIM, 1, 1);
    zero_stats<<<1, 512>>>();
    bn_stats<<<dim3(2, 128), 256>>>(C, n);
    bn_apply<<<nd_blocks, 256>>>(C, g1, be1, Dd, n);

    // ---------------- layer 2: GATConv(512 -> 1x512) ----------------
    gemm64<<<gemm_grid, 256>>>(Dd, W2, nullptr, A, n, DIM, DIM, 0, 0);
    attn_logits1<<<(n + 7) / 8, 256>>>(A, a2s, a2d, als, ald, n);
    init_layer<<<nd_blocks, 256>>>(mm, ss, n, B, b2, n * DIM);
    edge_pass<<<(Et + 255) / 256, 256>>>(ei, E, n, als, ald, mm, ss, 1, 0);
    edge_pass<<<(Et + 255) / 256, 256>>>(ei, E, n, als, ald, mm, ss, 1, 1);
    edge_agg<<<(Et + 1) / 2, 256>>>(ei, E, n, A, als, ald, mm, ss, B, 1);

    // ---------------- fc2 + relu + BN ----------------
    gemm64<<<gemm_grid, 256>>>(B, fc2w, fc2b, C, n, DIM, DIM, 1, 1);
    zero_stats<<<1, 512>>>();
    bn_stats<<<dim3(2, 128), 256>>>(C, n);
    bn_apply<<<nd_blocks, 256>>>(C, g2, be2, Dd, n);

    // ---------------- final linear + relu ----------------
    final_lin<<<(n * 32 + 255) / 256, 256>>>(Dd, linw, linb, out, n);
}

// round 3
// speedup vs baseline: 1.5333x; 1.5333x over previous
#include <cuda_runtime.h>
#include <math.h>

#define NMAX 20000
#define EMAX 320000
#define ETMAX (NMAX + EMAX)
#define DIM 512
#define H1 8
#define C1 64

// ---------------- scratch (static device memory; no allocations) -------------
__device__ float g_bufA[NMAX * DIM];   // GEMM outputs / GAT feature h
__device__ float g_bufB[NMAX * DIM];   // GAT aggregation output
__device__ float g_bufC[NMAX * DIM];   // fc output (post-relu)
__device__ float g_bufD[NMAX * DIM];   // BN output
__device__ float g_als[NMAX * H1];
__device__ float g_ald[NMAX * H1];
__device__ float g_sum[DIM];
__device__ float g_sumsq[DIM];
// CSR scratch
__device__ int g_cnt[NMAX];
__device__ int g_rowptr[NMAX + 1];
__device__ int g_cursor[NMAX];
__device__ int g_srcs[ETMAX];

// ================= CSR build ==================================================
__global__ void csr_zero(int n) {
    int i = blockIdx.x * blockDim.x + threadIdx.x;
    if (i < n) g_cnt[i] = 0;
}

__global__ void csr_hist(const int* __restrict__ ei, int E, int n) {
    int e = blockIdx.x * blockDim.x + threadIdx.x;
    if (e >= E + n) return;
    int dst = (e < E) ? ei[E + e] : e - E;
    atomicAdd(&g_cnt[dst], 1);
}

__global__ void csr_scan(int n, int Et) {   // single block, 1024 threads
    __shared__ int part[1024];
    int tid = threadIdx.x;
    int chunk = (n + 1023) / 1024;
    int lo = tid * chunk;
    int hi = lo + chunk; if (hi > n) hi = n; if (lo > n) lo = n;
    int s = 0;
    for (int i = lo; i < hi; i++) s += g_cnt[i];
    part[tid] = s;
    __syncthreads();
    for (int off = 1; off < 1024; off <<= 1) {
        int v = (tid >= off) ? part[tid - off] : 0;
        __syncthreads();
        part[tid] += v;
        __syncthreads();
    }
    int run = (tid == 0) ? 0 : part[tid - 1];
    for (int i = lo; i < hi; i++) {
        g_rowptr[i] = run;
        g_cursor[i] = run;
        run += g_cnt[i];
    }
    if (tid == 1023) g_rowptr[n] = Et;
}

__global__ void csr_scatter(const int* __restrict__ ei, int E, int n) {
    int e = blockIdx.x * blockDim.x + threadIdx.x;
    if (e >= E + n) return;
    int src, dst;
    if (e < E) { src = ei[e]; dst = ei[E + e]; }
    else       { src = dst = e - E; }
    int pos = atomicAdd(&g_cursor[dst], 1);
    g_srcs[pos] = src;
}

// ================= GEMM: C[M,N] = A[M,K] @ B[K,N] (+bias)(+relu) =============
// 128x128 tile, BK=8, 256 threads, 8x8 per thread, double-buffered smem.
// Requires N % 128 == 0, K % 8 == 0.
#define PA 132
__global__ __launch_bounds__(256) void gemm128(
    const float* __restrict__ A, const float* __restrict__ B,
    const float* __restrict__ bias, float* __restrict__ C,
    int M, int N, int K, int has_bias, int do_relu)
{
    __shared__ float As[2][8][PA];
    __shared__ float Bs[2][8][128];

    int tid = threadIdx.x;
    int m0 = blockIdx.y * 128;
    int n0 = blockIdx.x * 128;

    int a_row = tid >> 1;            // 0..127
    int a_col = (tid & 1) * 4;       // 0 or 4
    int b_row = tid >> 5;            // 0..7
    int b_col = (tid & 31) * 4;      // 0..124

    int ty = tid >> 4;               // 0..15 -> rows ty*8..+7
    int tx = tid & 15;               // 0..15 -> cols tx*8..+7

    float acc[8][8];
#pragma unroll
    for (int i = 0; i < 8; i++)
#pragma unroll
        for (int j = 0; j < 8; j++) acc[i][j] = 0.f;

    int gm_a = m0 + a_row;
    const float* Arow = A + (size_t)gm_a * K;

    // preload tile 0
    float4 ar, br;
    ar = (gm_a < M) ? *(const float4*)(Arow + a_col) : make_float4(0.f, 0.f, 0.f, 0.f);
    br = *(const float4*)(B + (size_t)b_row * N + n0 + b_col);
    As[0][a_col + 0][a_row] = ar.x;
    As[0][a_col + 1][a_row] = ar.y;
    As[0][a_col + 2][a_row] = ar.z;
    As[0][a_col + 3][a_row] = ar.w;
    *(float4*)&Bs[0][b_row][b_col] = br;
    __syncthreads();

    int buf = 0;
    for (int k0 = 0; k0 < K; k0 += 8) {
        bool has_next = (k0 + 8) < K;
        if (has_next) {
            ar = (gm_a < M) ? *(const float4*)(Arow + k0 + 8 + a_col)
                            : make_float4(0.f, 0.f, 0.f, 0.f);
            br = *(const float4*)(B + (size_t)(k0 + 8 + b_row) * N + n0 + b_col);
        }
#pragma unroll
        for (int kk = 0; kk < 8; kk++) {
            float a[8], b[8];
            *(float4*)&a[0] = *(const float4*)&As[buf][kk][ty * 8];
            *(float4*)&a[4] = *(const float4*)&As[buf][kk][ty * 8 + 4];
            *(float4*)&b[0] = *(const float4*)&Bs[buf][kk][tx * 8];
            *(float4*)&b[4] = *(const float4*)&Bs[buf][kk][tx * 8 + 4];
#pragma unroll
            for (int i = 0; i < 8; i++)
#pragma unroll
                for (int j = 0; j < 8; j++) acc[i][j] = fmaf(a[i], b[j], acc[i][j]);
        }
        if (has_next) {
            As[buf ^ 1][a_col + 0][a_row] = ar.x;
            As[buf ^ 1][a_col + 1][a_row] = ar.y;
            As[buf ^ 1][a_col + 2][a_row] = ar.z;
            As[buf ^ 1][a_col + 3][a_row] = ar.w;
            *(float4*)&Bs[buf ^ 1][b_row][b_col] = br;
            __syncthreads();
            buf ^= 1;
        }
    }

    // epilogue
#pragma unroll
    for (int i = 0; i < 8; i++) {
        int gm = m0 + ty * 8 + i;
        if (gm >= M) continue;
        int gn = n0 + tx * 8;
        float4 v0, v1;
        v0.x = acc[i][0]; v0.y = acc[i][1]; v0.z = acc[i][2]; v0.w = acc[i][3];
        v1.x = acc[i][4]; v1.y = acc[i][5]; v1.z = acc[i][6]; v1.w = acc[i][7];
        if (has_bias) {
            float4 b0 = *(const float4*)(bias + gn);
            float4 b1 = *(const float4*)(bias + gn + 4);
            v0.x += b0.x; v0.y += b0.y; v0.z += b0.z; v0.w += b0.w;
            v1.x += b1.x; v1.y += b1.y; v1.z += b1.z; v1.w += b1.w;
        }
        if (do_relu) {
            v0.x = fmaxf(v0.x, 0.f); v0.y = fmaxf(v0.y, 0.f);
            v0.z = fmaxf(v0.z, 0.f); v0.w = fmaxf(v0.w, 0.f);
            v1.x = fmaxf(v1.x, 0.f); v1.y = fmaxf(v1.y, 0.f);
            v1.z = fmaxf(v1.z, 0.f); v1.w = fmaxf(v1.w, 0.f);
        }
        *(float4*)(C + (size_t)gm * N + gn) = v0;
        *(float4*)(C + (size_t)gm * N + gn + 4) = v1;
    }
}

// ================= attention logits ==========================================
__global__ void attn_logits8(const float* __restrict__ h,
                             const float* __restrict__ a_s,
                             const float* __restrict__ a_d,
                             float* __restrict__ als, float* __restrict__ ald, int n)
{
    int node = blockIdx.x;
    if (node >= n) return;
    int w = threadIdx.x >> 5;
    int lane = threadIdx.x & 31;
    const float* row = h + (size_t)node * DIM + w * C1;
    float ss = 0.f, sd = 0.f;
#pragma unroll
    for (int c = lane; c < C1; c += 32) {
        float v = row[c];
        ss = fmaf(v, a_s[w * C1 + c], ss);
        sd = fmaf(v, a_d[w * C1 + c], sd);
    }
#pragma unroll
    for (int o = 16; o; o >>= 1) {
        ss += __shfl_down_sync(0xffffffffu, ss, o);
        sd += __shfl_down_sync(0xffffffffu, sd, o);
    }
    if (lane == 0) { als[node * 8 + w] = ss; ald[node * 8 + w] = sd; }
}

__global__ void attn_logits1(const float* __restrict__ h,
                             const float* __restrict__ a_s,
                             const float* __restrict__ a_d,
                             float* __restrict__ als, float* __restrict__ ald, int n)
{
    int warp = (blockIdx.x * blockDim.x + threadIdx.x) >> 5;
    int lane = threadIdx.x & 31;
    if (warp >= n) return;
    const float* row = h + (size_t)warp * DIM;
    float ss = 0.f, sd = 0.f;
#pragma unroll 4
    for (int c = lane; c < DIM; c += 32) {
        float v = row[c];
        ss = fmaf(v, a_s[c], ss);
        sd = fmaf(v, a_d[c], sd);
    }
#pragma unroll
    for (int o = 16; o; o >>= 1) {
        ss += __shfl_down_sync(0xffffffffu, ss, o);
        sd += __shfl_down_sync(0xffffffffu, sd, o);
    }
    if (lane == 0) { als[warp] = ss; ald[warp] = sd; }
}

// ================= fused GAT softmax+aggregate (CSR, no atomics) ==============
// H=8: one block per dst node; warp h handles head h (64 channels).
__global__ __launch_bounds__(256) void gat_agg8(
    const float* __restrict__ h, const float* __restrict__ als,
    const float* __restrict__ ald, const float* __restrict__ bias,
    float* __restrict__ out)
{
    int dst = blockIdx.x;
    int hh = threadIdx.x >> 5;
    int lane = threadIdx.x & 31;
    int r0 = g_rowptr[dst], r1 = g_rowptr[dst + 1];
    float aldv = ald[dst * 8 + hh];

    float mx = -1e30f;
    for (int i = r0 + lane; i < r1; i += 32) {
        int s = g_srcs[i];
        float ev = als[s * 8 + hh] + aldv;
        ev = (ev > 0.f) ? ev : 0.2f * ev;
        mx = fmaxf(mx, ev);
    }
#pragma unroll
    for (int o = 16; o; o >>= 1) mx = fmaxf(mx, __shfl_xor_sync(0xffffffffu, mx, o));

    float sum = 0.f;
    for (int i = r0 + lane; i < r1; i += 32) {
        int s = g_srcs[i];
        float ev = als[s * 8 + hh] + aldv;
        ev = (ev > 0.f) ? ev : 0.2f * ev;
        sum += __expf(ev - mx);
    }
#pragma unroll
    for (int o = 16; o; o >>= 1) sum += __shfl_xor_sync(0xffffffffu, sum, o);
    float inv_s = 1.f / sum;

    int c = hh * 64 + lane * 2;
    float2 acc = make_float2(0.f, 0.f);
    for (int i = r0; i < r1; i++) {
        int s = g_srcs[i];
        float ev = als[s * 8 + hh] + aldv;
        ev = (ev > 0.f) ? ev : 0.2f * ev;
        float w = __expf(ev - mx) * inv_s;
        float2 v = *(const float2*)(h + (size_t)s * DIM + c);
        acc.x = fmaf(w, v.x, acc.x);
        acc.y = fmaf(w, v.y, acc.y);
    }
    float2 bv = *(const float2*)(bias + c);
    acc.x += bv.x; acc.y += bv.y;
    *(float2*)(out + (size_t)dst * DIM + c) = acc;
}

// H=1: one block (256 threads) per dst node; each thread owns 2 channels.
__global__ __launch_bounds__(256) void gat_agg1(
    const float* __restrict__ h, const float* __restrict__ als,
    const float* __restrict__ ald, const float* __restrict__ bias,
    float* __restrict__ out)
{
    __shared__ float sh_mx, sh_inv;
    int dst = blockIdx.x;
    int tid = threadIdx.x;
    int r0 = g_rowptr[dst], r1 = g_rowptr[dst + 1];
    float aldv = ald[dst];

    if (tid < 32) {
        float mx = -1e30f;
        for (int i = r0 + tid; i < r1; i += 32) {
            int s = g_srcs[i];
            float ev = als[s] + aldv;
            ev = (ev > 0.f) ? ev : 0.2f * ev;
            mx = fmaxf(mx, ev);
        }
#pragma unroll
        for (int o = 16; o; o >>= 1) mx = fmaxf(mx, __shfl_xor_sync(0xffffffffu, mx, o));
        float sum = 0.f;
        for (int i = r0 + tid; i < r1; i += 32) {
            int s = g_srcs[i];
            float ev = als[s] + aldv;
            ev = (ev > 0.f) ? ev : 0.2f * ev;
            sum += __expf(ev - mx);
        }
#pragma unroll
        for (int o = 16; o; o >>= 1) sum += __shfl_xor_sync(0xffffffffu, sum, o);
        if (tid == 0) { sh_mx = mx; sh_inv = 1.f / sum; }
    }
    __syncthreads();
    float mx = sh_mx, inv_s = sh_inv;

    int c = tid * 2;
    float2 acc = make_float2(0.f, 0.f);
    for (int i = r0; i < r1; i++) {
        int s = g_srcs[i];
        float ev = als[s] + aldv;
        ev = (ev > 0.f) ? ev : 0.2f * ev;
        float w = __expf(ev - mx) * inv_s;
        float2 v = *(const float2*)(h + (size_t)s * DIM + c);
        acc.x = fmaf(w, v.x, acc.x);
        acc.y = fmaf(w, v.y, acc.y);
    }
    float2 bv = *(const float2*)(bias + c);
    acc.x += bv.x; acc.y += bv.y;
    *(float2*)(out + (size_t)dst * DIM + c) = acc;
}

// ================= BN =========================================================
__global__ void zero_stats() {
    int i = threadIdx.x;
    if (i < DIM) { g_sum[i] = 0.f; g_sumsq[i] = 0.f; }
}

__global__ void bn_stats(const float* __restrict__ x, int n)
{
    int col = blockIdx.x * 256 + threadIdx.x;   // gridDim.x == 2
    float sm = 0.f, sq = 0.f;
    for (int r = blockIdx.y; r < n; r += gridDim.y) {
        float v = x[(size_t)r * DIM + col];
        sm += v;
        sq = fmaf(v, v, sq);
    }
    atomicAdd(&g_sum[col], sm);
    atomicAdd(&g_sumsq[col], sq);
}

__global__ void bn_apply(const float* __restrict__ x,
                         const float* __restrict__ gamma, const float* __restrict__ beta,
                         float* __restrict__ y, int n)
{
    int i = blockIdx.x * blockDim.x + threadIdx.x;
    if (i >= n * DIM) return;
    int col = i & (DIM - 1);
    float inv_n = 1.f / (float)n;
    float mu = g_sum[col] * inv_n;
    float var = g_sumsq[col] * inv_n - mu * mu;
    y[i] = fmaf(gamma[col] * (x[i] - mu), rsqrtf(var + 1e-5f), beta[col]);
}

// ================= final linear [512 -> 2] + relu =============================
__global__ void final_lin(const float* __restrict__ h, const float* __restrict__ w,
                          const float* __restrict__ b, float* __restrict__ out, int n)
{
    int warp = (blockIdx.x * blockDim.x + threadIdx.x) >> 5;
    int lane = threadIdx.x & 31;
    if (warp >= n) return;
    const float* row = h + (size_t)warp * DIM;
    float a0 = 0.f, a1 = 0.f;
#pragma unroll 4
    for (int c = lane; c < DIM; c += 32) {
        float v = row[c];
        a0 = fmaf(v, w[c * 2 + 0], a0);
        a1 = fmaf(v, w[c * 2 + 1], a1);
    }
#pragma unroll
    for (int o = 16; o; o >>= 1) {
        a0 += __shfl_down_sync(0xffffffffu, a0, o);
        a1 += __shfl_down_sync(0xffffffffu, a1, o);
    }
    if (lane == 0) {
        out[warp * 2 + 0] = fmaxf(a0 + b[0], 0.f);
        out[warp * 2 + 1] = fmaxf(a1 + b[1], 0.f);
    }
}

// ------------------------------------------------------------------------------
extern "C" void kernel_launch(void* const* d_in, const int* in_sizes, int n_in,
                              void* d_out, int out_size)
{
    const float* x    = (const float*)d_in[0];
    const int*   ei   = (const int*)d_in[1];     // int32 edge indices
    const float* W1   = (const float*)d_in[2];
    const float* a1s  = (const float*)d_in[3];
    const float* a1d  = (const float*)d_in[4];
    const float* b1   = (const float*)d_in[5];
    const float* W2   = (const float*)d_in[6];
    const float* a2s  = (const float*)d_in[7];
    const float* a2d  = (const float*)d_in[8];
    const float* b2   = (const float*)d_in[9];
    const float* fc1w = (const float*)d_in[10];
    const float* fc1b = (const float*)d_in[11];
    const float* g1   = (const float*)d_in[12];
    const float* be1  = (const float*)d_in[13];
    const float* fc2w = (const float*)d_in[14];
    const float* fc2b = (const float*)d_in[15];
    const float* g2   = (const float*)d_in[16];
    const float* be2  = (const float*)d_in[17];
    const float* linw = (const float*)d_in[18];
    const float* linb = (const float*)d_in[19];
    float* out = (float*)d_out;

    int n = out_size / 2;        // 20000
    int E = in_sizes[1] / 2;     // 320000
    int Et = E + n;

    float *A, *B, *C, *Dd, *als, *ald;
    cudaGetSymbolAddress((void**)&A,   g_bufA);
    cudaGetSymbolAddress((void**)&B,   g_bufB);
    cudaGetSymbolAddress((void**)&C,   g_bufC);
    cudaGetSymbolAddress((void**)&Dd,  g_bufD);
    cudaGetSymbolAddress((void**)&als, g_als);
    cudaGetSymbolAddress((void**)&ald, g_ald);

    dim3 gemm_grid(DIM / 128, (n + 127) / 128);
    int nd_blocks = (n * DIM + 255) / 256;

    // ---------------- CSR build (once, reused by both layers) ----------------
    csr_zero<<<(n + 255) / 256, 256>>>(n);
    csr_hist<<<(Et + 255) / 256, 256>>>(ei, E, n);
    csr_scan<<<1, 1024>>>(n, Et);
    csr_scatter<<<(Et + 255) / 256, 256>>>(ei, E, n);

    // ---------------- layer 1: GATConv(128 -> 8x64) ----------------
    gemm128<<<gemm_grid, 256>>>(x, W1, nullptr, A, n, DIM, 128, 0, 0);
    attn_logits8<<<n, 256>>>(A, a1s, a1d, als, ald, n);
    gat_agg8<<<n, 256>>>(A, als, ald, b1, B);

    // ---------------- fc1 + relu + BN ----------------
    gemm128<<<gemm_grid, 256>>>(B, fc1w, fc1b, C, n, DIM, DIM, 1, 1);
    zero_stats<<<1, 512>>>();
    bn_stats<<<dim3(2, 128), 256>>>(C, n);
    bn_apply<<<nd_blocks, 256>>>(C, g1, be1, Dd, n);

    // ---------------- layer 2: GATConv(512 -> 1x512) ----------------
    gemm128<<<gemm_grid, 256>>>(Dd, W2, nullptr, A, n, DIM, DIM, 0, 0);
    attn_logits1<<<(n + 7) / 8, 256>>>(A, a2s, a2d, als, ald, n);
    gat_agg1<<<n, 256>>>(A, als, ald, b2, B);

    // ---------------- fc2 + relu + BN ----------------
    gemm128<<<gemm_grid, 256>>>(B, fc2w, fc2b, C, n, DIM, DIM, 1, 1);
    zero_stats<<<1, 512>>>();
    bn_stats<<<dim3(2, 128), 256>>>(C, n);
    bn_apply<<<nd_blocks, 256>>>(C, g2, be2, Dd, n);

    // ---------------- final linear + relu ----------------
    final_lin<<<(n * 32 + 255) / 256, 256>>>(Dd, linw, linb, out, n);
}

// round 4
// speedup vs baseline: 1.9385x; 1.2643x over previous
#include <cuda_runtime.h>
#include <math.h>

#define NMAX 20000
#define EMAX 320000
#define ETMAX (NMAX + EMAX)
#define DIM 512
#define H1 8
#define C1 64

// ---------------- scratch (static device memory; no allocations) -------------
__device__ float g_bufA[NMAX * DIM];
__device__ float g_bufB[NMAX * DIM];
__device__ float g_bufC[NMAX * DIM];
__device__ float g_bufD[NMAX * DIM];
__device__ float g_als[NMAX * H1];
__device__ float g_ald[NMAX * H1];
__device__ float g_sum[DIM];
__device__ float g_sumsq[DIM];
__device__ int g_cnt[NMAX];
__device__ int g_rowptr[NMAX + 1];
__device__ int g_cursor[NMAX];
__device__ int g_srcs[ETMAX];

// ================= CSR build ==================================================
__global__ void csr_zero(int n) {
    int i = blockIdx.x * blockDim.x + threadIdx.x;
    if (i < n) g_cnt[i] = 0;
}

__global__ void csr_hist(const int* __restrict__ ei, int E, int n) {
    int e = blockIdx.x * blockDim.x + threadIdx.x;
    if (e >= E + n) return;
    int dst = (e < E) ? ei[E + e] : e - E;
    atomicAdd(&g_cnt[dst], 1);
}

__global__ void csr_scan(int n, int Et) {   // single block, 1024 threads
    __shared__ int part[1024];
    int tid = threadIdx.x;
    int chunk = (n + 1023) / 1024;
    int lo = tid * chunk;
    int hi = lo + chunk; if (hi > n) hi = n; if (lo > n) lo = n;
    int s = 0;
    for (int i = lo; i < hi; i++) s += g_cnt[i];
    part[tid] = s;
    __syncthreads();
    for (int off = 1; off < 1024; off <<= 1) {
        int v = (tid >= off) ? part[tid - off] : 0;
        __syncthreads();
        part[tid] += v;
        __syncthreads();
    }
    int run = (tid == 0) ? 0 : part[tid - 1];
    for (int i = lo; i < hi; i++) {
        g_rowptr[i] = run;
        g_cursor[i] = run;
        run += g_cnt[i];
    }
    if (tid == 1023) g_rowptr[n] = Et;
}

__global__ void csr_scatter(const int* __restrict__ ei, int E, int n) {
    int e = blockIdx.x * blockDim.x + threadIdx.x;
    if (e >= E + n) return;
    int src, dst;
    if (e < E) { src = ei[e]; dst = ei[E + e]; }
    else       { src = dst = e - E; }
    int pos = atomicAdd(&g_cursor[dst], 1);
    g_srcs[pos] = src;
}

// ================= TF32 tensor-core GEMM (3xTF32 compensated) =================
// C[M,N] = A[M,K] @ B[K,N] (+bias)(+relu). N%128==0, K%16==0.
// 128x128 block tile, 8 warps (64x32 warp tile), BK=16, double-buffered smem.

__device__ __forceinline__ void split_tf32(float v, unsigned& hi, unsigned& lo) {
    unsigned h;
    asm("cvt.rna.tf32.f32 %0, %1;" : "=r"(h) : "f"(v));
    float r = v - __uint_as_float(h);
    unsigned l;
    asm("cvt.rna.tf32.f32 %0, %1;" : "=r"(l) : "f"(r));
    hi = h; lo = l;
}

__device__ __forceinline__ void mma_tf32(float* d, const unsigned* a, const unsigned* b) {
    asm volatile(
        "mma.sync.aligned.m16n8k8.row.col.f32.tf32.tf32.f32 "
        "{%0,%1,%2,%3}, {%4,%5,%6,%7}, {%8,%9}, {%0,%1,%2,%3};"
        : "+f"(d[0]), "+f"(d[1]), "+f"(d[2]), "+f"(d[3])
        : "r"(a[0]), "r"(a[1]), "r"(a[2]), "r"(a[3]), "r"(b[0]), "r"(b[1]));
}

#define GPAD 136   // floats; 136 % 32 == 8 -> conflict-free fragment reads

__global__ __launch_bounds__(256) void gemm_tf32(
    const float* __restrict__ A, const float* __restrict__ B,
    const float* __restrict__ bias, float* __restrict__ C,
    int M, int N, int K, int has_bias, int do_relu)
{
    __shared__ float As[2][16][GPAD];   // [k][m]
    __shared__ float Bs[2][16][GPAD];   // [k][n]

    int tid  = threadIdx.x;
    int warp = tid >> 5;
    int lane = tid & 31;
    int grp  = lane >> 2;    // 0..7
    int l4   = lane & 3;     // 0..3

    int m0 = blockIdx.y * 128;
    int n0 = blockIdx.x * 128;
    int wm = (warp >> 2) * 64;   // 0 or 64
    int wn = (warp & 3) * 32;    // 0,32,64,96

    float acc[4][4][4];
#pragma unroll
    for (int mi = 0; mi < 4; mi++)
#pragma unroll
        for (int ni = 0; ni < 4; ni++)
#pragma unroll
            for (int r = 0; r < 4; r++) acc[mi][ni][r] = 0.f;

    // gmem load assignments
    int a_row = tid >> 1;              // 0..127
    int a_k   = (tid & 1) * 8;         // 0 or 8 (covers 8 k via 2 float4)
    int b_k   = tid >> 4;              // 0..15
    int b_n   = (tid & 15) * 8;        // 0..120

    int gm_a = m0 + a_row;
    const float* Arow = A + (size_t)gm_a * K;

    // ---- preload tile 0 ----
    float4 a0v, a1v, b0v, b1v;
    if (gm_a < M) {
        a0v = *(const float4*)(Arow + a_k);
        a1v = *(const float4*)(Arow + a_k + 4);
    } else {
        a0v = make_float4(0.f, 0.f, 0.f, 0.f);
        a1v = a0v;
    }
    b0v = *(const float4*)(B + (size_t)b_k * N + n0 + b_n);
    b1v = *(const float4*)(B + (size_t)b_k * N + n0 + b_n + 4);

    As[0][a_k + 0][a_row] = a0v.x; As[0][a_k + 1][a_row] = a0v.y;
    As[0][a_k + 2][a_row] = a0v.z; As[0][a_k + 3][a_row] = a0v.w;
    As[0][a_k + 4][a_row] = a1v.x; As[0][a_k + 5][a_row] = a1v.y;
    As[0][a_k + 6][a_row] = a1v.z; As[0][a_k + 7][a_row] = a1v.w;
    *(float4*)&Bs[0][b_k][b_n]     = b0v;
    *(float4*)&Bs[0][b_k][b_n + 4] = b1v;
    __syncthreads();

    int buf = 0;
    for (int k0 = 0; k0 < K; k0 += 16) {
        bool has_next = (k0 + 16) < K;
        if (has_next) {
            if (gm_a < M) {
                a0v = *(const float4*)(Arow + k0 + 16 + a_k);
                a1v = *(const float4*)(Arow + k0 + 16 + a_k + 4);
            } else {
                a0v = make_float4(0.f, 0.f, 0.f, 0.f);
                a1v = a0v;
            }
            b0v = *(const float4*)(B + (size_t)(k0 + 16 + b_k) * N + n0 + b_n);
            b1v = *(const float4*)(B + (size_t)(k0 + 16 + b_k) * N + n0 + b_n + 4);
        }

#pragma unroll
        for (int kk = 0; kk < 16; kk += 8) {
            unsigned Ahi[4][4], Alo[4][4];
#pragma unroll
            for (int mi = 0; mi < 4; mi++) {
                int rm = wm + mi * 16 + grp;
                float v0 = As[buf][kk + l4][rm];
                float v1 = As[buf][kk + l4][rm + 8];
                float v2 = As[buf][kk + l4 + 4][rm];
                float v3 = As[buf][kk + l4 + 4][rm + 8];
                split_tf32(v0, Ahi[mi][0], Alo[mi][0]);
                split_tf32(v1, Ahi[mi][1], Alo[mi][1]);
                split_tf32(v2, Ahi[mi][2], Alo[mi][2]);
                split_tf32(v3, Ahi[mi][3], Alo[mi][3]);
            }
            unsigned Bhi[4][2], Blo[4][2];
#pragma unroll
            for (int ni = 0; ni < 4; ni++) {
                int cn = wn + ni * 8 + grp;
                float u0 = Bs[buf][kk + l4][cn];
                float u1 = Bs[buf][kk + l4 + 4][cn];
                split_tf32(u0, Bhi[ni][0], Blo[ni][0]);
                split_tf32(u1, Bhi[ni][1], Blo[ni][1]);
            }
#pragma unroll
            for (int mi = 0; mi < 4; mi++)
#pragma unroll
                for (int ni = 0; ni < 4; ni++) {
                    mma_tf32(acc[mi][ni], Ahi[mi], Bhi[ni]);
                    mma_tf32(acc[mi][ni], Ahi[mi], Blo[ni]);
                    mma_tf32(acc[mi][ni], Alo[mi], Bhi[ni]);
                }
        }

        if (has_next) {
            __syncthreads();
            int nb = buf ^ 1;
            As[nb][a_k + 0][a_row] = a0v.x; As[nb][a_k + 1][a_row] = a0v.y;
            As[nb][a_k + 2][a_row] = a0v.z; As[nb][a_k + 3][a_row] = a0v.w;
            As[nb][a_k + 4][a_row] = a1v.x; As[nb][a_k + 5][a_row] = a1v.y;
            As[nb][a_k + 6][a_row] = a1v.z; As[nb][a_k + 7][a_row] = a1v.w;
            *(float4*)&Bs[nb][b_k][b_n]     = b0v;
            *(float4*)&Bs[nb][b_k][b_n + 4] = b1v;
            __syncthreads();
            buf = nb;
        }
    }

    // ---- epilogue ----
#pragma unroll
    for (int mi = 0; mi < 4; mi++) {
        int r0 = m0 + wm + mi * 16 + grp;
        int r1 = r0 + 8;
#pragma unroll
        for (int ni = 0; ni < 4; ni++) {
            int c = n0 + wn + ni * 8 + l4 * 2;
            float2 v0 = make_float2(acc[mi][ni][0], acc[mi][ni][1]);
            float2 v1 = make_float2(acc[mi][ni][2], acc[mi][ni][3]);
            if (has_bias) {
                float2 bv = *(const float2*)(bias + c);
                v0.x += bv.x; v0.y += bv.y;
                v1.x += bv.x; v1.y += bv.y;
            }
            if (do_relu) {
                v0.x = fmaxf(v0.x, 0.f); v0.y = fmaxf(v0.y, 0.f);
                v1.x = fmaxf(v1.x, 0.f); v1.y = fmaxf(v1.y, 0.f);
            }
            if (r0 < M) *(float2*)(C + (size_t)r0 * N + c) = v0;
            if (r1 < M) *(float2*)(C + (size_t)r1 * N + c) = v1;
        }
    }
}

// ================= attention logits ==========================================
__global__ void attn_logits8(const float* __restrict__ h,
                             const float* __restrict__ a_s,
                             const float* __restrict__ a_d,
                             float* __restrict__ als, float* __restrict__ ald, int n)
{
    int node = blockIdx.x;
    if (node >= n) return;
    int w = threadIdx.x >> 5;
    int lane = threadIdx.x & 31;
    const float* row = h + (size_t)node * DIM + w * C1;
    float ss = 0.f, sd = 0.f;
#pragma unroll
    for (int c = lane; c < C1; c += 32) {
        float v = row[c];
        ss = fmaf(v, a_s[w * C1 + c], ss);
        sd = fmaf(v, a_d[w * C1 + c], sd);
    }
#pragma unroll
    for (int o = 16; o; o >>= 1) {
        ss += __shfl_down_sync(0xffffffffu, ss, o);
        sd += __shfl_down_sync(0xffffffffu, sd, o);
    }
    if (lane == 0) { als[node * 8 + w] = ss; ald[node * 8 + w] = sd; }
}

__global__ void attn_logits1(const float* __restrict__ h,
                             const float* __restrict__ a_s,
                             const float* __restrict__ a_d,
                             float* __restrict__ als, float* __restrict__ ald, int n)
{
    int warp = (blockIdx.x * blockDim.x + threadIdx.x) >> 5;
    int lane = threadIdx.x & 31;
    if (warp >= n) return;
    const float* row = h + (size_t)warp * DIM;
    float ss = 0.f, sd = 0.f;
#pragma unroll 4
    for (int c = lane; c < DIM; c += 32) {
        float v = row[c];
        ss = fmaf(v, a_s[c], ss);
        sd = fmaf(v, a_d[c], sd);
    }
#pragma unroll
    for (int o = 16; o; o >>= 1) {
        ss += __shfl_down_sync(0xffffffffu, ss, o);
        sd += __shfl_down_sync(0xffffffffu, sd, o);
    }
    if (lane == 0) { als[warp] = ss; ald[warp] = sd; }
}

// ================= fused GAT softmax+aggregate (CSR, no atomics) ==============
__global__ __launch_bounds__(256) void gat_agg8(
    const float* __restrict__ h, const float* __restrict__ als,
    const float* __restrict__ ald, const float* __restrict__ bias,
    float* __restrict__ out)
{
    int dst = blockIdx.x;
    int hh = threadIdx.x >> 5;
    int lane = threadIdx.x & 31;
    int r0 = g_rowptr[dst], r1 = g_rowptr[dst + 1];
    float aldv = ald[dst * 8 + hh];

    float mx = -1e30f;
    for (int i = r0 + lane; i < r1; i += 32) {
        int s = g_srcs[i];
        float ev = als[s * 8 + hh] + aldv;
        ev = (ev > 0.f) ? ev : 0.2f * ev;
        mx = fmaxf(mx, ev);
    }
#pragma unroll
    for (int o = 16; o; o >>= 1) mx = fmaxf(mx, __shfl_xor_sync(0xffffffffu, mx, o));

    float sum = 0.f;
    for (int i = r0 + lane; i < r1; i += 32) {
        int s = g_srcs[i];
        float ev = als[s * 8 + hh] + aldv;
        ev = (ev > 0.f) ? ev : 0.2f * ev;
        sum += __expf(ev - mx);
    }
#pragma unroll
    for (int o = 16; o; o >>= 1) sum += __shfl_xor_sync(0xffffffffu, sum, o);
    float inv_s = 1.f / sum;

    int c = hh * 64 + lane * 2;
    float2 acc = make_float2(0.f, 0.f);
    for (int i = r0; i < r1; i++) {
        int s = g_srcs[i];
        float ev = als[s * 8 + hh] + aldv;
        ev = (ev > 0.f) ? ev : 0.2f * ev;
        float w = __expf(ev - mx) * inv_s;
        float2 v = *(const float2*)(h + (size_t)s * DIM + c);
        acc.x = fmaf(w, v.x, acc.x);
        acc.y = fmaf(w, v.y, acc.y);
    }
    float2 bv = *(const float2*)(bias + c);
    acc.x += bv.x; acc.y += bv.y;
    *(float2*)(out + (size_t)dst * DIM + c) = acc;
}

__global__ __launch_bounds__(256) void gat_agg1(
    const float* __restrict__ h, const float* __restrict__ als,
    const float* __restrict__ ald, const float* __restrict__ bias,
    float* __restrict__ out)
{
    __shared__ float sh_mx, sh_inv;
    int dst = blockIdx.x;
    int tid = threadIdx.x;
    int r0 = g_rowptr[dst], r1 = g_rowptr[dst + 1];
    float aldv = ald[dst];

    if (tid < 32) {
        float mx = -1e30f;
        for (int i = r0 + tid; i < r1; i += 32) {
            int s = g_srcs[i];
            float ev = als[s] + aldv;
            ev = (ev > 0.f) ? ev : 0.2f * ev;
            mx = fmaxf(mx, ev);
        }
#pragma unroll
        for (int o = 16; o; o >>= 1) mx = fmaxf(mx, __shfl_xor_sync(0xffffffffu, mx, o));
        float sum = 0.f;
        for (int i = r0 + tid; i < r1; i += 32) {
            int s = g_srcs[i];
            float ev = als[s] + aldv;
            ev = (ev > 0.f) ? ev : 0.2f * ev;
            sum += __expf(ev - mx);
        }
#pragma unroll
        for (int o = 16; o; o >>= 1) sum += __shfl_xor_sync(0xffffffffu, sum, o);
        if (tid == 0) { sh_mx = mx; sh_inv = 1.f / sum; }
    }
    __syncthreads();
    float mx = sh_mx, inv_s = sh_inv;

    int c = tid * 2;
    float2 acc = make_float2(0.f, 0.f);
    for (int i = r0; i < r1; i++) {
        int s = g_srcs[i];
        float ev = als[s] + aldv;
        ev = (ev > 0.f) ? ev : 0.2f * ev;
        float w = __expf(ev - mx) * inv_s;
        float2 v = *(const float2*)(h + (size_t)s * DIM + c);
        acc.x = fmaf(w, v.x, acc.x);
        acc.y = fmaf(w, v.y, acc.y);
    }
    float2 bv = *(const float2*)(bias + c);
    acc.x += bv.x; acc.y += bv.y;
    *(float2*)(out + (size_t)dst * DIM + c) = acc;
}

// ================= BN =========================================================
__global__ void zero_stats() {
    int i = threadIdx.x;
    if (i < DIM) { g_sum[i] = 0.f; g_sumsq[i] = 0.f; }
}

__global__ void bn_stats(const float* __restrict__ x, int n)
{
    int col = blockIdx.x * 256 + threadIdx.x;   // gridDim.x == 2
    float sm = 0.f, sq = 0.f;
    for (int r = blockIdx.y; r < n; r += gridDim.y) {
        float v = x[(size_t)r * DIM + col];
        sm += v;
        sq = fmaf(v, v, sq);
    }
    atomicAdd(&g_sum[col], sm);
    atomicAdd(&g_sumsq[col], sq);
}

__global__ void bn_apply(const float* __restrict__ x,
                         const float* __restrict__ gamma, const float* __restrict__ beta,
                         float* __restrict__ y, int n)
{
    int i = blockIdx.x * blockDim.x + threadIdx.x;
    if (i >= n * DIM) return;
    int col = i & (DIM - 1);
    float inv_n = 1.f / (float)n;
    float mu = g_sum[col] * inv_n;
    float var = g_sumsq[col] * inv_n - mu * mu;
    y[i] = fmaf(gamma[col] * (x[i] - mu), rsqrtf(var + 1e-5f), beta[col]);
}

// ================= final linear [512 -> 2] + relu =============================
__global__ void final_lin(const float* __restrict__ h, const float* __restrict__ w,
                          const float* __restrict__ b, float* __restrict__ out, int n)
{
    int warp = (blockIdx.x * blockDim.x + threadIdx.x) >> 5;
    int lane = threadIdx.x & 31;
    if (warp >= n) return;
    const float* row = h + (size_t)warp * DIM;
    float a0 = 0.f, a1 = 0.f;
#pragma unroll 4
    for (int c = lane; c < DIM; c += 32) {
        float v = row[c];
        a0 = fmaf(v, w[c * 2 + 0], a0);
        a1 = fmaf(v, w[c * 2 + 1], a1);
    }
#pragma unroll
    for (int o = 16; o; o >>= 1) {
        a0 += __shfl_down_sync(0xffffffffu, a0, o);
        a1 += __shfl_down_sync(0xffffffffu, a1, o);
    }
    if (lane == 0) {
        out[warp * 2 + 0] = fmaxf(a0 + b[0], 0.f);
        out[warp * 2 + 1] = fmaxf(a1 + b[1], 0.f);
    }
}

// ------------------------------------------------------------------------------
extern "C" void kernel_launch(void* const* d_in, const int* in_sizes, int n_in,
                              void* d_out, int out_size)
{
    const float* x    = (const float*)d_in[0];
    const int*   ei   = (const int*)d_in[1];     // int32 edge indices
    const float* W1   = (const float*)d_in[2];
    const float* a1s  = (const float*)d_in[3];
    const float* a1d  = (const float*)d_in[4];
    const float* b1   = (const float*)d_in[5];
    const float* W2   = (const float*)d_in[6];
    const float* a2s  = (const float*)d_in[7];
    const float* a2d  = (const float*)d_in[8];
    const float* b2   = (const float*)d_in[9];
    const float* fc1w = (const float*)d_in[10];
    const float* fc1b = (const float*)d_in[11];
    const float* g1   = (const float*)d_in[12];
    const float* be1  = (const float*)d_in[13];
    const float* fc2w = (const float*)d_in[14];
    const float* fc2b = (const float*)d_in[15];
    const float* g2   = (const float*)d_in[16];
    const float* be2  = (const float*)d_in[17];
    const float* linw = (const float*)d_in[18];
    const float* linb = (const float*)d_in[19];
    float* out = (float*)d_out;

    int n = out_size / 2;        // 20000
    int E = in_sizes[1] / 2;     // 320000
    int Et = E + n;

    float *A, *B, *C, *Dd, *als, *ald;
    cudaGetSymbolAddress((void**)&A,   g_bufA);
    cudaGetSymbolAddress((void**)&B,   g_bufB);
    cudaGetSymbolAddress((void**)&C,   g_bufC);
    cudaGetSymbolAddress((void**)&Dd,  g_bufD);
    cudaGetSymbolAddress((void**)&als, g_als);
    cudaGetSymbolAddress((void**)&ald, g_ald);

    dim3 gemm_grid(DIM / 128, (n + 127) / 128);
    int nd_blocks = (n * DIM + 255) / 256;

    // ---------------- CSR build (once, reused by both layers) ----------------
    csr_zero<<<(n + 255) / 256, 256>>>(n);
    csr_hist<<<(Et + 255) / 256, 256>>>(ei, E, n);
    csr_scan<<<1, 1024>>>(n, Et);
    csr_scatter<<<(Et + 255) / 256, 256>>>(ei, E, n);

    // ---------------- layer 1: GATConv(128 -> 8x64) ----------------
    gemm_tf32<<<gemm_grid, 256>>>(x, W1, nullptr, A, n, DIM, 128, 0, 0);
    attn_logits8<<<n, 256>>>(A, a1s, a1d, als, ald, n);
    gat_agg8<<<n, 256>>>(A, als, ald, b1, B);

    // ---------------- fc1 + relu + BN ----------------
    gemm_tf32<<<gemm_grid, 256>>>(B, fc1w, fc1b, C, n, DIM, DIM, 1, 1);
    zero_stats<<<1, 512>>>();
    bn_stats<<<dim3(2, 128), 256>>>(C, n);
    bn_apply<<<nd_blocks, 256>>>(C, g1, be1, Dd, n);

    // ---------------- layer 2: GATConv(512 -> 1x512) ----------------
    gemm_tf32<<<gemm_grid, 256>>>(Dd, W2, nullptr, A, n, DIM, DIM, 0, 0);
    attn_logits1<<<(n + 7) / 8, 256>>>(A, a2s, a2d, als, ald, n);
    gat_agg1<<<n, 256>>>(A, als, ald, b2, B);

    // ---------------- fc2 + relu + BN ----------------
    gemm_tf32<<<gemm_grid, 256>>>(B, fc2w, fc2b, C, n, DIM, DIM, 1, 1);
    zero_stats<<<1, 512>>>();
    bn_stats<<<dim3(2, 128), 256>>>(C, n);
    bn_apply<<<nd_blocks, 256>>>(C, g2, be2, Dd, n);

    // ---------------- final linear + relu ----------------
    final_lin<<<(n * 32 + 255) / 256, 256>>>(Dd, linw, linb, out, n);
}